// round 8
// baseline (speedup 1.0000x reference)
#include <cuda_runtime.h>
#include <cuda_bf16.h>
#include <cstdint>

#define NPTS 100000
#define K3   27
#define MT   128
#define NTHR 256            // 8 warps: 4(M) x 2(N)
#define NSTG 3
// stage layout (words): [A hi 2560 | A lo 2560 | B hi 1280 | B lo 1280]
// A row = 80 bytes (64B data = 32 bf16, 16B pad) -> conflict-free ldmatrix (5r mod 8 perm)
#define STGW  7680
#define STGB  (STGW*4)      // 30720 B
#define ALOB  (2560*4)
#define BOFFB (5120*4)
#define BLOB  (1280*4)
// header: neighbor table + biases
#define NBW   (MT*K3)       // 3456 words
#define BIASW 192
#define HDRW  (NBW + BIASW) // 3648 words = 14592 B (divisible by 128)
#define SMEM_BYTES (HDRW*4 + NSTG*STGB)   // 106752 -> 2 CTAs/SM

// ---------------- device scratch ----------------
__device__ __align__(16) unsigned g_xh[(size_t)NPTS * 64];
__device__ __align__(16) unsigned g_xl[(size_t)NPTS * 64];
__device__ __align__(16) unsigned g_hh[(size_t)NPTS * 64];
__device__ __align__(16) unsigned g_hl[(size_t)NPTS * 64];
__device__ __align__(16) unsigned g_W00p[K3 * 10240];
__device__ __align__(16) unsigned g_WcatB[K3 * 10240];
__device__ __align__(16) unsigned g_W10p[10240];
__device__ __align__(16) unsigned g_W12p[5120];

// ---------------- helpers ----------------
__device__ __forceinline__ unsigned short f2bf(float f) {
    return __bfloat16_as_ushort(__float2bfloat16_rn(f));
}
__device__ __forceinline__ float bf2f(unsigned short u) {
    return __bfloat162float(__ushort_as_bfloat16(u));
}
__device__ __forceinline__ void split2(float a, float b, unsigned& hi, unsigned& lo) {
    unsigned short ha = f2bf(a), hb = f2bf(b);
    float ra = a - bf2f(ha), rb = b - bf2f(hb);
    hi = (unsigned)ha | ((unsigned)hb << 16);
    lo = (unsigned)f2bf(ra) | ((unsigned)f2bf(rb) << 16);
}
__device__ __forceinline__ unsigned smem_u32(const void* p) {
    unsigned a;
    asm("{ .reg .u64 t; cvta.to.shared.u64 t, %1; cvt.u32.u64 %0, t; }" : "=r"(a) : "l"(p));
    return a;
}
__device__ __forceinline__ void cp16(unsigned dst, const void* src, unsigned srcsize) {
    asm volatile("cp.async.cg.shared.global [%0], [%1], 16, %2;"
                 :: "r"(dst), "l"(src), "r"(srcsize));
}
#define CP_COMMIT() asm volatile("cp.async.commit_group;")
#define CP_WAIT1()  asm volatile("cp.async.wait_group 1;")
#define CP_WAIT0()  asm volatile("cp.async.wait_group 0;")

__device__ __forceinline__ void ldsm4(unsigned& r0, unsigned& r1, unsigned& r2, unsigned& r3,
                                      unsigned a) {
    asm volatile("ldmatrix.sync.aligned.m8n8.x4.shared.b16 {%0,%1,%2,%3}, [%4];"
                 : "=r"(r0), "=r"(r1), "=r"(r2), "=r"(r3) : "r"(a));
}
__device__ __forceinline__ void mma_bf16(float* d, const unsigned* a, unsigned b0, unsigned b1) {
    asm volatile(
        "mma.sync.aligned.m16n8k16.row.col.f32.bf16.bf16.f32 "
        "{%0,%1,%2,%3}, {%4,%5,%6,%7}, {%8,%9}, {%0,%1,%2,%3};\n"
        : "+f"(d[0]), "+f"(d[1]), "+f"(d[2]), "+f"(d[3])
        : "r"(a[0]), "r"(a[1]), "r"(a[2]), "r"(a[3]), "r"(b0), "r"(b1));
}
__device__ __forceinline__ void wsplit(unsigned* chunkBase, int off, int slot, float v) {
    __nv_bfloat16* ph = (__nv_bfloat16*)(chunkBase + off);
    __nv_bfloat16* pl = (__nv_bfloat16*)(chunkBase + 1280 + off);
    unsigned short h = f2bf(v);
    ph[slot] = __ushort_as_bfloat16(h);
    pl[slot] = __float2bfloat16_rn(v - bf2f(h));
}

// ---------------- prep kernels ----------------
__global__ void split_x(const float* __restrict__ x) {
    size_t t = (size_t)blockIdx.x * blockDim.x + threadIdx.x;
    if (t >= (size_t)NPTS * 32) return;
    float4 v = ((const float4*)x)[t];
    unsigned h0, l0, h1, l1;
    split2(v.x, v.y, h0, l0);
    split2(v.z, v.w, h1, l1);
    ((uint2*)g_xh)[t] = make_uint2(h0, h1);
    ((uint2*)g_xl)[t] = make_uint2(l0, l1);
}

#define P_W00  (K3 * 128 * 64)
#define P_WCAT (K3 * 64 * 128)
#define P_TOT  (P_W00 + P_WCAT + 128*64 + 64*64)

__global__ void pack_weights(const float* __restrict__ W00, const float* __restrict__ W01,
                             const float* __restrict__ W11, const float* __restrict__ W10,
                             const float* __restrict__ W12) {
    int t = blockIdx.x * blockDim.x + threadIdx.x;
    if (t < P_W00) {
        int k = t / 8192, rem = t % 8192, c = rem / 64, n = rem % 64;
        wsplit(g_W00p + k * 10240 + (c >> 5) * 2560,
               n * 20 + ((c & 31) >> 1), c & 1, W00[t]);
        return;
    }
    t -= P_W00;
    if (t < P_WCAT) {
        int k = t / 8192, rem = t % 8192, half = rem / 4096, r2 = rem % 4096;
        int c = r2 / 64, n = r2 % 64;
        float v = half ? W11[k * 4096 + c * 64 + n] : W01[k * 4096 + c * 64 + n];
        wsplit(g_WcatB + k * 10240 + (half * 2 + (c >> 5)) * 2560,
               n * 20 + ((c & 31) >> 1), c & 1, v);
        return;
    }
    t -= P_WCAT;
    if (t < 128 * 64) {
        int c = t / 64, n = t % 64;
        wsplit(g_W10p + (c >> 5) * 2560, n * 20 + ((c & 31) >> 1), c & 1, W10[t]);
        return;
    }
    t -= 128 * 64;
    if (t < 64 * 64) {
        int c = t / 64, n = t % 64;
        wsplit(g_W12p + (c >> 5) * 2560, n * 20 + ((c & 31) >> 1), c & 1, W12[t]);
    }
}

// ---- inner stage: [128m x 32k] x [32k x 64n], 3-term bf16 split ----
__device__ __forceinline__ void mma_stage(unsigned Ab, unsigned Bb,
                                          float acc[2][4][4],
                                          unsigned aOff, unsigned bOff) {
    #pragma unroll
    for (int g = 0; g < 2; ++g) {
        unsigned ah[2][4], al[2][4], bh[2][4], bl[2][4];
        #pragma unroll
        for (int mb = 0; mb < 2; ++mb) {
            unsigned a = Ab + aOff + g * 32 + mb * 1280;
            ldsm4(ah[mb][0], ah[mb][1], ah[mb][2], ah[mb][3], a);
            ldsm4(al[mb][0], al[mb][1], al[mb][2], al[mb][3], a + ALOB);
        }
        #pragma unroll
        for (int p = 0; p < 2; ++p) {
            unsigned b = Bb + bOff + g * 32 + p * 1280;
            ldsm4(bh[p][0], bh[p][1], bh[p][2], bh[p][3], b);
            ldsm4(bl[p][0], bl[p][1], bl[p][2], bl[p][3], b + BLOB);
        }
        #pragma unroll
        for (int mb = 0; mb < 2; ++mb)
            #pragma unroll
            for (int nt = 0; nt < 4; ++nt) {
                const int p = nt >> 1, u = (nt & 1) * 2;
                mma_bf16(acc[mb][nt], ah[mb], bh[p][u], bh[p][u + 1]);
                mma_bf16(acc[mb][nt], ah[mb], bl[p][u], bl[p][u + 1]);
                mma_bf16(acc[mb][nt], al[mb], bh[p][u], bh[p][u + 1]);
            }
    }
}

// =============== kernel A: h = [ relu(conv0_0(x)+b00) | relu(x@W10+b10) ] ===============
__global__ __launch_bounds__(NTHR, 2)
void convA(const int* __restrict__ nbr,
           const float* __restrict__ b00, const float* __restrict__ b10) {
    extern __shared__ unsigned sm[];
    int* nb = (int*)sm;
    float* bias = (float*)(sm + NBW);
    const unsigned sStg = smem_u32(sm) + HDRW * 4;
    const int tid = threadIdx.x, lane = tid & 31, warp = tid >> 5;
    const int wm = warp >> 1, wn = warp & 1;
    const int base = blockIdx.x * MT, rows = min(MT, NPTS - base);
    const int r = tid >> 1, q = tid & 1;

    for (int i = tid; i < rows * K3; i += NTHR) nb[i] = nbr[(size_t)base * K3 + i];
    if (tid < 64) { bias[tid] = b00[tid]; bias[64 + tid] = b10[tid]; }
    __syncthreads();

    const unsigned aOff = (unsigned)((wm * 32 + ((lane >> 3) & 1) * 8 + (lane & 7)) * 80
                                     + ((lane >> 4) & 1) * 16);
    const unsigned bOff = (unsigned)((wn * 32 + ((lane >> 4) & 1) * 8 + (lane & 7)) * 80
                                     + ((lane >> 3) & 1) * 16);
    const unsigned dA0 = sStg + (unsigned)(r * 80 + q * 32);   // per-thread A dst base

    auto stage = [&](int s) {
        const unsigned bufD = (unsigned)(s % NSTG) * STGB;
        const int tap = s >> 2, kc = s & 3;
        int idx;
        if (r < rows) idx = (tap < K3) ? nb[r * K3 + tap] : (base + r);
        else          idx = NPTS;
        const unsigned sz = (idx < NPTS) ? 16u : 0u;
        const size_t so = (size_t)idx * 64 + kc * 16 + q * 8;
        const unsigned dA = dA0 + bufD;
        cp16(dA,             g_xh + so,     sz);
        cp16(dA + 16,        g_xh + so + 4, sz);
        cp16(dA + ALOB,      g_xl + so,     sz);
        cp16(dA + ALOB + 16, g_xl + so + 4, sz);
        const unsigned* Wg = ((tap < K3) ? (g_W00p + tap * 10240) : g_W10p) + kc * 2560;
        #pragma unroll
        for (int j = 0; j < 3; ++j) {
            const int i = j * NTHR + tid;
            if (i < 640) cp16(sStg + bufD + BOFFB + (unsigned)i * 16u, Wg + i * 4, 16u);
        }
        CP_COMMIT();
    };

    float acc0[2][4][4] = {};
    float acc1[2][4][4] = {};

    const int S = 112;
    stage(0); stage(1);
    for (int s = 0; s < S; ++s) {
        if (s < S - 1) { CP_WAIT1(); } else { CP_WAIT0(); }
        __syncthreads();
        if (s + 2 < S) stage(s + 2);
        const unsigned Ab = sStg + (unsigned)(s % NSTG) * STGB;
        mma_stage(Ab, Ab + BOFFB, ((s >> 2) < K3) ? acc0 : acc1, aOff, bOff);
    }

    #pragma unroll
    for (int mb = 0; mb < 2; ++mb) {
        const int r0 = wm * 32 + mb * 16 + (lane >> 2);
        const int p0 = base + r0, p1 = p0 + 8;
        #pragma unroll
        for (int nt = 0; nt < 4; ++nt) {
            const int col = wn * 32 + nt * 8 + (lane & 3) * 2;
            const float ba0 = bias[col], ba1 = bias[col + 1];
            const float bb0 = bias[64 + col], bb1 = bias[64 + col + 1];
            unsigned hi, lo;
            if (p0 < NPTS) {
                split2(fmaxf(acc0[mb][nt][0] + ba0, 0.f), fmaxf(acc0[mb][nt][1] + ba1, 0.f), hi, lo);
                g_hh[(size_t)p0 * 64 + (col >> 1)] = hi; g_hl[(size_t)p0 * 64 + (col >> 1)] = lo;
                split2(fmaxf(acc1[mb][nt][0] + bb0, 0.f), fmaxf(acc1[mb][nt][1] + bb1, 0.f), hi, lo);
                g_hh[(size_t)p0 * 64 + 32 + (col >> 1)] = hi; g_hl[(size_t)p0 * 64 + 32 + (col >> 1)] = lo;
            }
            if (p1 < NPTS) {
                split2(fmaxf(acc0[mb][nt][2] + ba0, 0.f), fmaxf(acc0[mb][nt][3] + ba1, 0.f), hi, lo);
                g_hh[(size_t)p1 * 64 + (col >> 1)] = hi; g_hl[(size_t)p1 * 64 + (col >> 1)] = lo;
                split2(fmaxf(acc1[mb][nt][2] + bb0, 0.f), fmaxf(acc1[mb][nt][3] + bb1, 0.f), hi, lo);
                g_hh[(size_t)p1 * 64 + 32 + (col >> 1)] = hi; g_hl[(size_t)p1 * 64 + 32 + (col >> 1)] = lo;
            }
        }
    }
}

// ==== kernel B: out = [conv0_1(h0)+b01 | relu(conv1_1(h1)+b11)@W12+b12] + x ====
__global__ __launch_bounds__(NTHR, 2)
void convB(const int* __restrict__ nbr,
           const float* __restrict__ b01, const float* __restrict__ b11,
           const float* __restrict__ b12, const float* __restrict__ x,
           float* __restrict__ out) {
    extern __shared__ unsigned sm[];
    int* nb = (int*)sm;
    float* bias = (float*)(sm + NBW);
    const unsigned sStg = smem_u32(sm) + HDRW * 4;
    const int tid = threadIdx.x, lane = tid & 31, warp = tid >> 5;
    const int wm = warp >> 1, wn = warp & 1;
    const int base = blockIdx.x * MT, rows = min(MT, NPTS - base);
    const int r = tid >> 1, q = tid & 1;

    for (int i = tid; i < rows * K3; i += NTHR) nb[i] = nbr[(size_t)base * K3 + i];
    if (tid < 64) { bias[tid] = b01[tid]; bias[64 + tid] = b11[tid]; bias[128 + tid] = b12[tid]; }
    __syncthreads();

    const unsigned aOff = (unsigned)((wm * 32 + ((lane >> 3) & 1) * 8 + (lane & 7)) * 80
                                     + ((lane >> 4) & 1) * 16);
    const unsigned bOff = (unsigned)((wn * 32 + ((lane >> 4) & 1) * 8 + (lane & 7)) * 80
                                     + ((lane >> 3) & 1) * 16);
    const unsigned dA0 = sStg + (unsigned)(r * 80 + q * 32);

    auto stage = [&](int s) {
        const unsigned bufD = (unsigned)(s % NSTG) * STGB;
        const int tap = s >> 2, kc = s & 3;
        const int idx = (r < rows) ? nb[r * K3 + tap] : NPTS;
        const unsigned sz = (idx < NPTS) ? 16u : 0u;
        const size_t so = (size_t)idx * 64 + kc * 16 + q * 8;
        const unsigned dA = dA0 + bufD;
        cp16(dA,             g_hh + so,     sz);
        cp16(dA + 16,        g_hh + so + 4, sz);
        cp16(dA + ALOB,      g_hl + so,     sz);
        cp16(dA + ALOB + 16, g_hl + so + 4, sz);
        const unsigned* Wg = g_WcatB + tap * 10240 + kc * 2560;
        #pragma unroll
        for (int j = 0; j < 3; ++j) {
            const int i = j * NTHR + tid;
            if (i < 640) cp16(sStg + bufD + BOFFB + (unsigned)i * 16u, Wg + i * 4, 16u);
        }
        CP_COMMIT();
    };

    float acc0[2][4][4] = {};
    float acc1[2][4][4] = {};

    const int S = 108;
    stage(0); stage(1);
    for (int s = 0; s < S; ++s) {
        if (s < S - 1) { CP_WAIT1(); } else { CP_WAIT0(); }
        __syncthreads();
        if (s + 2 < S) stage(s + 2);
        const unsigned Ab = sStg + (unsigned)(s % NSTG) * STGB;
        mma_stage(Ab, Ab + BOFFB, ((s & 3) < 2) ? acc0 : acc1, aOff, bOff);
    }

    // ---- epilogue: store out0 (+b01 +x); stage h1b split into stage buffers 0/1 ----
    #pragma unroll
    for (int mb = 0; mb < 2; ++mb) {
        const int r0 = wm * 32 + mb * 16 + (lane >> 2), r1 = r0 + 8;
        const int p0 = base + r0, p1 = base + r1;
        #pragma unroll
        for (int nt = 0; nt < 4; ++nt) {
            const int col = wn * 32 + nt * 8 + (lane & 3) * 2;
            const int ch = col >> 5, kl = col & 31;
            unsigned* bA = sm + HDRW + ch * STGW;
            const float bh0 = bias[64 + col], bh1 = bias[64 + col + 1];
            unsigned hi, lo;
            split2(fmaxf(acc1[mb][nt][0] + bh0, 0.f), fmaxf(acc1[mb][nt][1] + bh1, 0.f), hi, lo);
            bA[r0 * 20 + (kl >> 1)] = hi; bA[2560 + r0 * 20 + (kl >> 1)] = lo;
            split2(fmaxf(acc1[mb][nt][2] + bh0, 0.f), fmaxf(acc1[mb][nt][3] + bh1, 0.f), hi, lo);
            bA[r1 * 20 + (kl >> 1)] = hi; bA[2560 + r1 * 20 + (kl >> 1)] = lo;
            const float bo0 = bias[col], bo1 = bias[col + 1];
            if (p0 < NPTS) {
                float2 xv = *(const float2*)(x + (size_t)p0 * 128 + col);
                *(float2*)(out + (size_t)p0 * 128 + col) =
                    make_float2(acc0[mb][nt][0] + bo0 + xv.x, acc0[mb][nt][1] + bo1 + xv.y);
            }
            if (p1 < NPTS) {
                float2 xv = *(const float2*)(x + (size_t)p1 * 128 + col);
                *(float2*)(out + (size_t)p1 * 128 + col) =
                    make_float2(acc0[mb][nt][2] + bo0 + xv.x, acc0[mb][nt][3] + bo1 + xv.y);
            }
        }
    }
    // copy W12 chunk images into stage buffers 0/1 B regions
    #pragma unroll
    for (int j = 0; j < 5; ++j) {
        const int w = (j * 256 + tid) * 4;
        const int ch = w / 2560, off = w % 2560;
        *(uint4*)(sm + HDRW + ch * STGW + 5120 + off) = *(const uint4*)(g_W12p + w);
    }
    __syncthreads();

    // ---- 1x1 epilogue GEMM: acc2 = h1b @ W12 ----
    float acc2[2][4][4] = {};
    #pragma unroll
    for (int ch = 0; ch < 2; ++ch) {
        const unsigned Ab = sStg + (unsigned)ch * STGB;
        mma_stage(Ab, Ab + BOFFB, acc2, aOff, bOff);
    }

    #pragma unroll
    for (int mb = 0; mb < 2; ++mb) {
        const int r0 = wm * 32 + mb * 16 + (lane >> 2);
        const int p0 = base + r0, p1 = p0 + 8;
        #pragma unroll
        for (int nt = 0; nt < 4; ++nt) {
            const int col = wn * 32 + nt * 8 + (lane & 3) * 2;
            const float bv0 = bias[128 + col], bv1 = bias[128 + col + 1];
            if (p0 < NPTS) {
                float2 xv = *(const float2*)(x + (size_t)p0 * 128 + 64 + col);
                *(float2*)(out + (size_t)p0 * 128 + 64 + col) =
                    make_float2(acc2[mb][nt][0] + bv0 + xv.x, acc2[mb][nt][1] + bv1 + xv.y);
            }
            if (p1 < NPTS) {
                float2 xv = *(const float2*)(x + (size_t)p1 * 128 + 64 + col);
                *(float2*)(out + (size_t)p1 * 128 + 64 + col) =
                    make_float2(acc2[mb][nt][2] + bv0 + xv.x, acc2[mb][nt][3] + bv1 + xv.y);
            }
        }
    }
}

// ---------------- launch ----------------
extern "C" void kernel_launch(void* const* d_in, const int* in_sizes, int n_in,
                              void* d_out, int out_size) {
    const float* x   = (const float*)d_in[0];
    const int*   nbr = (const int*)  d_in[1];
    const float* W00 = (const float*)d_in[2];
    const float* b00 = (const float*)d_in[3];
    const float* W01 = (const float*)d_in[4];
    const float* b01 = (const float*)d_in[5];
    const float* W10 = (const float*)d_in[6];
    const float* b10 = (const float*)d_in[7];
    const float* W11 = (const float*)d_in[8];
    const float* b11 = (const float*)d_in[9];
    const float* W12 = (const float*)d_in[10];
    const float* b12 = (const float*)d_in[11];
    float* out = (float*)d_out;

    cudaFuncSetAttribute(convA, cudaFuncAttributeMaxDynamicSharedMemorySize, SMEM_BYTES);
    cudaFuncSetAttribute(convB, cudaFuncAttributeMaxDynamicSharedMemorySize, SMEM_BYTES);

    split_x<<<(NPTS * 32 + 255) / 256, 256>>>(x);
    pack_weights<<<(P_TOT + 255) / 256, 256>>>(W00, W01, W11, W10, W12);
    const int grid = (NPTS + MT - 1) / MT;   // 782
    convA<<<grid, NTHR, SMEM_BYTES>>>(nbr, b00, b10);
    convB<<<grid, NTHR, SMEM_BYTES>>>(nbr, b01, b11, b12, x, out);
}

// round 9
// speedup vs baseline: 2.0544x; 2.0544x over previous
#include <cuda_runtime.h>
#include <cuda_fp16.h>
#include <cstdint>

#define NPTS 100000
#define K3   27
#define MT   128
#define NTHR 256            // 8 warps: 4(M) x 2(N)
#define NSTG 3
// stage layout (bytes): [A: 128 rows x 144B | B: 64 rows x 144B]
// row = 128B data (64 fp16, K-chunk 64) + 16B pad -> conflict-free ldmatrix (9r mod 8 perm)
#define STGB  27648
#define BOFFB 18432
#define SMEM_BYTES (NSTG*STGB)   // 82944 -> 2 CTAs/SM

// ---------------- device scratch ----------------
__device__ __align__(16) unsigned g_x16[(size_t)NPTS * 64];   // x fp16x2 words (128 ch)
__device__ __align__(16) unsigned g_h16[(size_t)NPTS * 64];   // h fp16x2 words [h0|h1]
// weight chunk images: [64k x 64n] as 64 n-rows x 36 words (128B data + 16B pad) = 2304 words
__device__ __align__(16) unsigned g_W00p[K3 * 4608];          // per tap: 2 chunks
__device__ __align__(16) unsigned g_Wcat[K3 * 4608];          // chunk0 = W01, chunk1 = W11
__device__ __align__(16) unsigned g_W10p[4608];               // 2 chunks
__device__ __align__(16) unsigned g_W12p[2304];               // 1 chunk

// ---------------- helpers ----------------
__device__ __forceinline__ unsigned smem_u32(const void* p) {
    unsigned a;
    asm("{ .reg .u64 t; cvta.to.shared.u64 t, %1; cvt.u32.u64 %0, t; }" : "=r"(a) : "l"(p));
    return a;
}
__device__ __forceinline__ void cp16(unsigned dst, const void* src, unsigned srcsize) {
    asm volatile("cp.async.cg.shared.global [%0], [%1], 16, %2;"
                 :: "r"(dst), "l"(src), "r"(srcsize));
}
#define CP_COMMIT() asm volatile("cp.async.commit_group;")
#define CP_WAIT1()  asm volatile("cp.async.wait_group 1;")
#define CP_WAIT0()  asm volatile("cp.async.wait_group 0;")

__device__ __forceinline__ void ldsm4(unsigned& r0, unsigned& r1, unsigned& r2, unsigned& r3,
                                      unsigned a) {
    asm volatile("ldmatrix.sync.aligned.m8n8.x4.shared.b16 {%0,%1,%2,%3}, [%4];"
                 : "=r"(r0), "=r"(r1), "=r"(r2), "=r"(r3) : "r"(a));
}
__device__ __forceinline__ void mma_f16(float* d, const unsigned* a, unsigned b0, unsigned b1) {
    asm volatile(
        "mma.sync.aligned.m16n8k16.row.col.f32.f16.f16.f32 "
        "{%0,%1,%2,%3}, {%4,%5,%6,%7}, {%8,%9}, {%0,%1,%2,%3};\n"
        : "+f"(d[0]), "+f"(d[1]), "+f"(d[2]), "+f"(d[3])
        : "r"(a[0]), "r"(a[1]), "r"(a[2]), "r"(a[3]), "r"(b0), "r"(b1));
}
__device__ __forceinline__ unsigned packh2(float a, float b) {
    __half2 h = __floats2half2_rn(a, b);
    return *(unsigned*)&h;
}
__device__ __forceinline__ void wput(unsigned* arr, int word, int slot, float v) {
    ((__half*)arr)[(size_t)word * 2 + slot] = __float2half_rn(v);
}

// ---------------- prep kernels ----------------
__global__ void split_x(const float* __restrict__ x) {
    size_t t = (size_t)blockIdx.x * blockDim.x + threadIdx.x;
    if (t >= (size_t)NPTS * 32) return;
    float4 v = ((const float4*)x)[t];
    ((uint2*)g_x16)[t] = make_uint2(packh2(v.x, v.y), packh2(v.z, v.w));
}

#define P_W00  (K3 * 128 * 64)
#define P_WCAT (K3 * 64 * 128)
#define P_TOT  (P_W00 + P_WCAT + 128*64 + 64*64)

__global__ void pack_weights(const float* __restrict__ W00, const float* __restrict__ W01,
                             const float* __restrict__ W11, const float* __restrict__ W10,
                             const float* __restrict__ W12) {
    int t = blockIdx.x * blockDim.x + threadIdx.x;
    if (t < P_W00) {                       // W00[k][c 0..127][n 0..63]
        int k = t / 8192, rem = t % 8192, c = rem / 64, n = rem % 64;
        wput(g_W00p + k * 4608 + (c >> 6) * 2304, n * 36 + ((c & 63) >> 1), c & 1, W00[t]);
        return;
    }
    t -= P_W00;
    if (t < P_WCAT) {                      // half0 = W01, half1 = W11; c 0..63
        int k = t / 8192, rem = t % 8192, half = rem / 4096, r2 = rem % 4096;
        int c = r2 / 64, n = r2 % 64;
        float v = half ? W11[k * 4096 + c * 64 + n] : W01[k * 4096 + c * 64 + n];
        wput(g_Wcat + k * 4608 + half * 2304, n * 36 + (c >> 1), c & 1, v);
        return;
    }
    t -= P_WCAT;
    if (t < 128 * 64) {                    // W10[c 0..127][n]
        int c = t / 64, n = t % 64;
        wput(g_W10p + (c >> 6) * 2304, n * 36 + ((c & 63) >> 1), c & 1, W10[t]);
        return;
    }
    t -= 128 * 64;
    if (t < 64 * 64) {
        int c = t / 64, n = t % 64;
        wput(g_W12p, n * 36 + (c >> 1), c & 1, W12[t]);
    }
}

// ---- inner stage: [128m x 64k] x [64k x 64n] fp16, ldmatrix frags ----
__device__ __forceinline__ void mma_stage(unsigned Ab, unsigned Bb,
                                          float acc[2][4][4],
                                          unsigned aOff, unsigned bOff) {
    #pragma unroll
    for (int g = 0; g < 4; ++g) {
        unsigned a[2][4], b[2][4];
        #pragma unroll
        for (int mb = 0; mb < 2; ++mb)
            ldsm4(a[mb][0], a[mb][1], a[mb][2], a[mb][3], Ab + aOff + g * 32 + mb * 2304);
        #pragma unroll
        for (int p = 0; p < 2; ++p)
            ldsm4(b[p][0], b[p][1], b[p][2], b[p][3], Bb + bOff + g * 32 + p * 2304);
        #pragma unroll
        for (int mb = 0; mb < 2; ++mb)
            #pragma unroll
            for (int nt = 0; nt < 4; ++nt) {
                const int p = nt >> 1, u = (nt & 1) * 2;
                mma_f16(acc[mb][nt], a[mb], b[p][u], b[p][u + 1]);
            }
    }
}

// =============== kernel A: h = [ relu(conv0_0(x)+b00) | relu(x@W10+b10) ] ===============
__global__ __launch_bounds__(NTHR, 2)
void convA(const int* __restrict__ nbr,
           const float* __restrict__ b00, const float* __restrict__ b10) {
    extern __shared__ unsigned sm[];
    const unsigned sStg = smem_u32(sm);
    const int tid = threadIdx.x, lane = tid & 31, warp = tid >> 5;
    const int wm = warp >> 1, wn = warp & 1;
    const int base = blockIdx.x * MT, rows = min(MT, NPTS - base);
    const int r = tid >> 1, q = tid & 1;

    const unsigned aOff = (unsigned)((wm * 32 + ((lane >> 3) & 1) * 8 + (lane & 7)) * 144
                                     + ((lane >> 4) & 1) * 16);
    const unsigned bOff = (unsigned)((wn * 32 + ((lane >> 4) & 1) * 8 + (lane & 7)) * 144
                                     + ((lane >> 3) & 1) * 16);
    const unsigned dA0 = sStg + (unsigned)(r * 144 + q * 64);

    const int S = 56;   // 28 taps x 2 K-chunks
    auto tapidx = [&](int s) -> int {
        if (s >= S || r >= rows) return NPTS;
        const int tap = s >> 1;
        return (tap < K3) ? __ldg(&nbr[(size_t)(base + r) * K3 + tap]) : (base + r);
    };
    auto stage = [&](int s, int idx) {
        const unsigned bufD = (unsigned)(s % NSTG) * STGB;
        const int tap = s >> 1, kc = s & 1;
        const unsigned sz = (idx < NPTS) ? 16u : 0u;
        const unsigned* src = g_x16 + (size_t)idx * 64 + kc * 32 + q * 16;
        const unsigned dA = dA0 + bufD;
        cp16(dA,      src,      sz);
        cp16(dA + 16, src + 4,  sz);
        cp16(dA + 32, src + 8,  sz);
        cp16(dA + 48, src + 12, sz);
        const unsigned* Wg = ((tap < K3) ? (g_W00p + tap * 4608) : g_W10p) + kc * 2304;
        #pragma unroll
        for (int j = 0; j < 3; ++j) {
            const int i = j * NTHR + tid;
            if (i < 576) cp16(sStg + bufD + BOFFB + (unsigned)i * 16u, Wg + i * 4, 16u);
        }
        CP_COMMIT();
    };

    float acc0[2][4][4] = {};
    float acc1[2][4][4] = {};

    int id0 = tapidx(0), id1 = tapidx(1);
    stage(0, id0); stage(1, id1);
    int idN = tapidx(2);
    for (int s = 0; s < S; ++s) {
        if (s < S - 1) { CP_WAIT1(); } else { CP_WAIT0(); }
        __syncthreads();
        if (s + 2 < S) stage(s + 2, idN);
        idN = tapidx(s + 3);
        const unsigned Ab = sStg + (unsigned)(s % NSTG) * STGB;
        mma_stage(Ab, Ab + BOFFB, (s < 54) ? acc0 : acc1, aOff, bOff);
    }

    // epilogue: relu + bias -> h fp16
    #pragma unroll
    for (int mb = 0; mb < 2; ++mb) {
        const int r0 = wm * 32 + mb * 16 + (lane >> 2);
        const int p0 = base + r0, p1 = p0 + 8;
        #pragma unroll
        for (int nt = 0; nt < 4; ++nt) {
            const int col = wn * 32 + nt * 8 + (lane & 3) * 2;
            const float ba0 = __ldg(&b00[col]), ba1 = __ldg(&b00[col + 1]);
            const float bb0 = __ldg(&b10[col]), bb1 = __ldg(&b10[col + 1]);
            if (p0 < NPTS) {
                g_h16[(size_t)p0 * 64 + (col >> 1)] =
                    packh2(fmaxf(acc0[mb][nt][0] + ba0, 0.f), fmaxf(acc0[mb][nt][1] + ba1, 0.f));
                g_h16[(size_t)p0 * 64 + 32 + (col >> 1)] =
                    packh2(fmaxf(acc1[mb][nt][0] + bb0, 0.f), fmaxf(acc1[mb][nt][1] + bb1, 0.f));
            }
            if (p1 < NPTS) {
                g_h16[(size_t)p1 * 64 + (col >> 1)] =
                    packh2(fmaxf(acc0[mb][nt][2] + ba0, 0.f), fmaxf(acc0[mb][nt][3] + ba1, 0.f));
                g_h16[(size_t)p1 * 64 + 32 + (col >> 1)] =
                    packh2(fmaxf(acc1[mb][nt][2] + bb0, 0.f), fmaxf(acc1[mb][nt][3] + bb1, 0.f));
            }
        }
    }
}

// ==== kernel B: out = [conv0_1(h0)+b01 | relu(conv1_1(h1)+b11)@W12+b12] + x ====
__global__ __launch_bounds__(NTHR, 2)
void convB(const int* __restrict__ nbr,
           const float* __restrict__ b01, const float* __restrict__ b11,
           const float* __restrict__ b12, const float* __restrict__ x,
           float* __restrict__ out) {
    extern __shared__ unsigned sm[];
    const unsigned sStg = smem_u32(sm);
    const int tid = threadIdx.x, lane = tid & 31, warp = tid >> 5;
    const int wm = warp >> 1, wn = warp & 1;
    const int base = blockIdx.x * MT, rows = min(MT, NPTS - base);
    const int r = tid >> 1, q = tid & 1;

    const unsigned aOff = (unsigned)((wm * 32 + ((lane >> 3) & 1) * 8 + (lane & 7)) * 144
                                     + ((lane >> 4) & 1) * 16);
    const unsigned bOff = (unsigned)((wn * 32 + ((lane >> 4) & 1) * 8 + (lane & 7)) * 144
                                     + ((lane >> 3) & 1) * 16);
    const unsigned dA0 = sStg + (unsigned)(r * 144 + q * 64);

    const int S = 54;   // 27 taps x 2 K-chunks (kc0: h0@W01, kc1: h1@W11)
    auto tapidx = [&](int s) -> int {
        if (s >= S || r >= rows) return NPTS;
        return __ldg(&nbr[(size_t)(base + r) * K3 + (s >> 1)]);
    };
    auto stage = [&](int s, int idx) {
        const unsigned bufD = (unsigned)(s % NSTG) * STGB;
        const int tap = s >> 1, kc = s & 1;
        const unsigned sz = (idx < NPTS) ? 16u : 0u;
        const unsigned* src = g_h16 + (size_t)idx * 64 + kc * 32 + q * 16;
        const unsigned dA = dA0 + bufD;
        cp16(dA,      src,      sz);
        cp16(dA + 16, src + 4,  sz);
        cp16(dA + 32, src + 8,  sz);
        cp16(dA + 48, src + 12, sz);
        const unsigned* Wg = g_Wcat + tap * 4608 + kc * 2304;
        #pragma unroll
        for (int j = 0; j < 3; ++j) {
            const int i = j * NTHR + tid;
            if (i < 576) cp16(sStg + bufD + BOFFB + (unsigned)i * 16u, Wg + i * 4, 16u);
        }
        CP_COMMIT();
    };

    float acc0[2][4][4] = {};
    float acc1[2][4][4] = {};

    int id0 = tapidx(0), id1 = tapidx(1);
    stage(0, id0); stage(1, id1);
    int idN = tapidx(2);
    for (int s = 0; s < S; ++s) {
        if (s < S - 1) { CP_WAIT1(); } else { CP_WAIT0(); }
        __syncthreads();
        if (s + 2 < S) stage(s + 2, idN);
        idN = tapidx(s + 3);
        const unsigned Ab = sStg + (unsigned)(s % NSTG) * STGB;
        mma_stage(Ab, Ab + BOFFB, (s & 1) ? acc1 : acc0, aOff, bOff);
    }

    // ---- epilogue: store out0 (+b01 +x); stage h1b = relu(acc1+b11) fp16 into buf0 A ----
    // buf0 last read at stage 51 (two barriers before loop exit) -> safe to overwrite.
    #pragma unroll
    for (int mb = 0; mb < 2; ++mb) {
        const int r0 = wm * 32 + mb * 16 + (lane >> 2), r1 = r0 + 8;
        const int p0 = base + r0, p1 = base + r1;
        #pragma unroll
        for (int nt = 0; nt < 4; ++nt) {
            const int col = wn * 32 + nt * 8 + (lane & 3) * 2;
            const float bh0 = __ldg(&b11[col]), bh1 = __ldg(&b11[col + 1]);
            sm[r0 * 36 + (col >> 1)] =
                packh2(fmaxf(acc1[mb][nt][0] + bh0, 0.f), fmaxf(acc1[mb][nt][1] + bh1, 0.f));
            sm[r1 * 36 + (col >> 1)] =
                packh2(fmaxf(acc1[mb][nt][2] + bh0, 0.f), fmaxf(acc1[mb][nt][3] + bh1, 0.f));
            const float bo0 = __ldg(&b01[col]), bo1 = __ldg(&b01[col + 1]);
            if (p0 < NPTS) {
                float2 xv = *(const float2*)(x + (size_t)p0 * 128 + col);
                *(float2*)(out + (size_t)p0 * 128 + col) =
                    make_float2(acc0[mb][nt][0] + bo0 + xv.x, acc0[mb][nt][1] + bo1 + xv.y);
            }
            if (p1 < NPTS) {
                float2 xv = *(const float2*)(x + (size_t)p1 * 128 + col);
                *(float2*)(out + (size_t)p1 * 128 + col) =
                    make_float2(acc0[mb][nt][2] + bo0 + xv.x, acc0[mb][nt][3] + bo1 + xv.y);
            }
        }
    }
    // copy W12 chunk image into buf0 B region
    #pragma unroll
    for (int j = 0; j < 3; ++j) {
        const int i = j * NTHR + tid;
        if (i < 576) ((uint4*)(sm + BOFFB / 4))[i] = ((const uint4*)g_W12p)[i];
    }
    __syncthreads();

    // ---- 1x1 epilogue GEMM: acc2 = h1b @ W12 (K=64, one stage) ----
    float acc2[2][4][4] = {};
    mma_stage(sStg, sStg + BOFFB, acc2, aOff, bOff);

    #pragma unroll
    for (int mb = 0; mb < 2; ++mb) {
        const int r0 = wm * 32 + mb * 16 + (lane >> 2);
        const int p0 = base + r0, p1 = p0 + 8;
        #pragma unroll
        for (int nt = 0; nt < 4; ++nt) {
            const int col = wn * 32 + nt * 8 + (lane & 3) * 2;
            const float bv0 = __ldg(&b12[col]), bv1 = __ldg(&b12[col + 1]);
            if (p0 < NPTS) {
                float2 xv = *(const float2*)(x + (size_t)p0 * 128 + 64 + col);
                *(float2*)(out + (size_t)p0 * 128 + 64 + col) =
                    make_float2(acc2[mb][nt][0] + bv0 + xv.x, acc2[mb][nt][1] + bv1 + xv.y);
            }
            if (p1 < NPTS) {
                float2 xv = *(const float2*)(x + (size_t)p1 * 128 + 64 + col);
                *(float2*)(out + (size_t)p1 * 128 + 64 + col) =
                    make_float2(acc2[mb][nt][2] + bv0 + xv.x, acc2[mb][nt][3] + bv1 + xv.y);
            }
        }
    }
}

// ---------------- launch ----------------
extern "C" void kernel_launch(void* const* d_in, const int* in_sizes, int n_in,
                              void* d_out, int out_size) {
    const float* x   = (const float*)d_in[0];
    const int*   nbr = (const int*)  d_in[1];
    const float* W00 = (const float*)d_in[2];
    const float* b00 = (const float*)d_in[3];
    const float* W01 = (const float*)d_in[4];
    const float* b01 = (const float*)d_in[5];
    const float* W10 = (const float*)d_in[6];
    const float* b10 = (const float*)d_in[7];
    const float* W11 = (const float*)d_in[8];
    const float* b11 = (const float*)d_in[9];
    const float* W12 = (const float*)d_in[10];
    const float* b12 = (const float*)d_in[11];
    float* out = (float*)d_out;

    cudaFuncSetAttribute(convA, cudaFuncAttributeMaxDynamicSharedMemorySize, SMEM_BYTES);
    cudaFuncSetAttribute(convB, cudaFuncAttributeMaxDynamicSharedMemorySize, SMEM_BYTES);

    split_x<<<(NPTS * 32 + 255) / 256, 256>>>(x);
    pack_weights<<<(P_TOT + 255) / 256, 256>>>(W00, W01, W11, W10, W12);
    const int grid = (NPTS + MT - 1) / MT;   // 782
    convA<<<grid, NTHR, SMEM_BYTES>>>(nbr, b00, b10);
    convB<<<grid, NTHR, SMEM_BYTES>>>(nbr, b01, b11, b12, x, out);
}

// round 10
// speedup vs baseline: 3.0546x; 1.4869x over previous
#include <cuda_runtime.h>
#include <cuda_fp16.h>
#include <cstdint>

#define NPTS 100000
#define K3   27
#define MT   128
#define NTHR 256            // 8 warps: 4(M) x 2(N)
// stage (bytes): [A: 128 rows x 144B | B: 64 rows x 144B]; row = 128B data + 16B pad
#define STGB  27648
#define BOFFB 18432
#define SMEM_BYTES (3*STGB)   // 82944 -> 2 CTAs/SM

// ---------------- device scratch ----------------
__device__ __align__(16) unsigned g_x16[(size_t)NPTS * 64];   // x fp16x2 words
__device__ __align__(16) unsigned g_h16[(size_t)NPTS * 64];   // h fp16x2 words [h0|h1]
// weight chunk images, 2304 words each, linear in stage index: base + s*2304
__device__ __align__(16) unsigned g_W00p[K3 * 4608];
__device__ __align__(16) unsigned g_Wcat[K3 * 4608];
__device__ __align__(16) unsigned g_W10p[4608];
__device__ __align__(16) unsigned g_W12p[2304];

// ---------------- helpers ----------------
__device__ __forceinline__ unsigned smem_u32(const void* p) {
    unsigned a;
    asm("{ .reg .u64 t; cvta.to.shared.u64 t, %1; cvt.u32.u64 %0, t; }" : "=r"(a) : "l"(p));
    return a;
}
__device__ __forceinline__ void cp16(unsigned dst, const void* src, unsigned srcsize) {
    asm volatile("cp.async.cg.shared.global [%0], [%1], 16, %2;"
                 :: "r"(dst), "l"(src), "r"(srcsize));
}
#define CP_COMMIT() asm volatile("cp.async.commit_group;")
#define CP_WAIT1()  asm volatile("cp.async.wait_group 1;")
#define CP_WAIT0()  asm volatile("cp.async.wait_group 0;")

__device__ __forceinline__ void ldsm4(unsigned& r0, unsigned& r1, unsigned& r2, unsigned& r3,
                                      unsigned a) {
    asm volatile("ldmatrix.sync.aligned.m8n8.x4.shared.b16 {%0,%1,%2,%3}, [%4];"
                 : "=r"(r0), "=r"(r1), "=r"(r2), "=r"(r3) : "r"(a));
}
__device__ __forceinline__ void mma_f16(float* d, const unsigned* a, unsigned b0, unsigned b1) {
    asm volatile(
        "mma.sync.aligned.m16n8k16.row.col.f32.f16.f16.f32 "
        "{%0,%1,%2,%3}, {%4,%5,%6,%7}, {%8,%9}, {%0,%1,%2,%3};\n"
        : "+f"(d[0]), "+f"(d[1]), "+f"(d[2]), "+f"(d[3])
        : "r"(a[0]), "r"(a[1]), "r"(a[2]), "r"(a[3]), "r"(b0), "r"(b1));
}
__device__ __forceinline__ unsigned packh2(float a, float b) {
    __half2 h = __floats2half2_rn(a, b);
    return *(unsigned*)&h;
}
__device__ __forceinline__ void wput(unsigned* arr, int word, int slot, float v) {
    ((__half*)arr)[(size_t)word * 2 + slot] = __float2half_rn(v);
}

// ---------------- prep kernels ----------------
__global__ void split_x(const float* __restrict__ x) {
    size_t t = (size_t)blockIdx.x * blockDim.x + threadIdx.x;
    if (t >= (size_t)NPTS * 32) return;
    float4 v = ((const float4*)x)[t];
    ((uint2*)g_x16)[t] = make_uint2(packh2(v.x, v.y), packh2(v.z, v.w));
}

#define P_W00  (K3 * 128 * 64)
#define P_WCAT (K3 * 64 * 128)
#define P_TOT  (P_W00 + P_WCAT + 128*64 + 64*64)

__global__ void pack_weights(const float* __restrict__ W00, const float* __restrict__ W01,
                             const float* __restrict__ W11, const float* __restrict__ W10,
                             const float* __restrict__ W12) {
    int t = blockIdx.x * blockDim.x + threadIdx.x;
    if (t < P_W00) {                       // W00[k][c 0..127][n 0..63]
        int k = t / 8192, rem = t % 8192, c = rem / 64, n = rem % 64;
        wput(g_W00p + k * 4608 + (c >> 6) * 2304, n * 36 + ((c & 63) >> 1), c & 1, W00[t]);
        return;
    }
    t -= P_W00;
    if (t < P_WCAT) {                      // half0 = W01, half1 = W11; c 0..63
        int k = t / 8192, rem = t % 8192, half = rem / 4096, r2 = rem % 4096;
        int c = r2 / 64, n = r2 % 64;
        float v = half ? W11[k * 4096 + c * 64 + n] : W01[k * 4096 + c * 64 + n];
        wput(g_Wcat + k * 4608 + half * 2304, n * 36 + (c >> 1), c & 1, v);
        return;
    }
    t -= P_WCAT;
    if (t < 128 * 64) {                    // W10[c 0..127][n]
        int c = t / 64, n = t % 64;
        wput(g_W10p + (c >> 6) * 2304, n * 36 + ((c & 63) >> 1), c & 1, W10[t]);
        return;
    }
    t -= 128 * 64;
    if (t < 64 * 64) {
        int c = t / 64, n = t % 64;
        wput(g_W12p, n * 36 + (c >> 1), c & 1, W12[t]);
    }
}

// ---- inner stage: [128m x 64k] x [64k x 64n] fp16 ----
__device__ __forceinline__ void mma_stage(unsigned Ab, float acc[2][4][4],
                                          unsigned aOff, unsigned bOff) {
    const unsigned Bb = Ab + BOFFB;
    #pragma unroll
    for (int g = 0; g < 4; ++g) {
        unsigned a[2][4], b[2][4];
        #pragma unroll
        for (int mb = 0; mb < 2; ++mb)
            ldsm4(a[mb][0], a[mb][1], a[mb][2], a[mb][3], Ab + aOff + g * 32 + mb * 2304);
        #pragma unroll
        for (int p = 0; p < 2; ++p)
            ldsm4(b[p][0], b[p][1], b[p][2], b[p][3], Bb + bOff + g * 32 + p * 2304);
        #pragma unroll
        for (int mb = 0; mb < 2; ++mb)
            #pragma unroll
            for (int nt = 0; nt < 4; ++nt) {
                const int p = nt >> 1, u = (nt & 1) * 2;
                mma_f16(acc[mb][nt], a[mb], b[p][u], b[p][u + 1]);
            }
    }
}

// =============== kernel A: h = [ relu(conv0_0(x)+b00) | relu(x@W10+b10) ] ===============
__global__ __launch_bounds__(NTHR, 2)
void convA(const int* __restrict__ nbr,
           const float* __restrict__ b00, const float* __restrict__ b10) {
    extern __shared__ unsigned sm[];
    const unsigned sStg = smem_u32(sm);
    const int tid = threadIdx.x, lane = tid & 31, warp = tid >> 5;
    const int wm = warp >> 1, wn = warp & 1;
    const int base = blockIdx.x * MT, rows = min(MT, NPTS - base);
    const int r = tid >> 1, q = tid & 1;
    const bool inval = (r >= rows);
    const int* nbrP = nbr + (size_t)(base + (inval ? 0 : r)) * K3;
    const int selfIdx = inval ? NPTS : (base + r);

    const unsigned aOff = (unsigned)((wm*32 + ((lane>>3)&1)*8 + (lane&7))*144 + ((lane>>4)&1)*16);
    const unsigned bOff = (unsigned)((wn*32 + ((lane>>4)&1)*8 + (lane&7))*144 + ((lane>>3)&1)*16);
    const unsigned dA0 = sStg + (unsigned)(r*144 + q*64);
    const int qw = q * 16;

    auto stage = [&](unsigned bufD, int kcw, const unsigned* wsrc, int idx) {
        const unsigned sz = (idx < NPTS) ? 16u : 0u;
        const unsigned* src = g_x16 + (size_t)(unsigned)idx * 64u + kcw + qw;
        const unsigned dA = dA0 + bufD;
        cp16(dA,      src,      sz);
        cp16(dA + 16, src + 4,  sz);
        cp16(dA + 32, src + 8,  sz);
        cp16(dA + 48, src + 12, sz);
        const unsigned wD = sStg + bufD + BOFFB + (unsigned)tid * 16u;
        const unsigned* ws = wsrc + tid * 4;
        cp16(wD,            ws,            16u);
        cp16(wD + 256*16u,  ws + 256*4,    16u);
        if (tid < 64) cp16(wD + 512*16u, ws + 512*4, 16u);
        CP_COMMIT();
    };

    float acc0[2][4][4] = {};
    float acc1[2][4][4] = {};

    int idUse = inval ? NPTS : __ldg(&nbrP[0]);
    int idPre = inval ? NPTS : __ldg(&nbrP[1]);
    stage(0, 0, g_W00p, idUse);
    stage(STGB, 32, g_W00p + 2304, idUse);

    const unsigned* wp = g_W00p + 2 * 2304;
    for (int it = 0; it < 8; ++it) {
        #pragma unroll
        for (int u = 0; u < 6; ++u) {
            CP_WAIT1(); __syncthreads();
            if ((u & 1) == 0) {
                idUse = idPre;
                idPre = inval ? NPTS : __ldg(&nbrP[it * 3 + (u >> 1) + 2]);
            }
            stage(((u + 2) % 3) * STGB, (u & 1) * 32, wp + u * 2304, idUse);
            mma_stage(sStg + (u % 3) * STGB, acc0, aOff, bOff);
        }
        wp += 6 * 2304;
    }
    // tail: stages 48..55 (buffers: stage k lives in buf k%3)
    CP_WAIT1(); __syncthreads();                               // s=48
    idUse = idPre; idPre = inval ? NPTS : __ldg(&nbrP[26]);
    stage(2*STGB, 0, g_W00p + 50*2304, idUse);
    mma_stage(sStg,            acc0, aOff, bOff);
    CP_WAIT1(); __syncthreads();                               // s=49
    stage(0,      32, g_W00p + 51*2304, idUse);
    mma_stage(sStg + STGB,     acc0, aOff, bOff);
    CP_WAIT1(); __syncthreads();                               // s=50
    idUse = idPre;
    stage(STGB,   0,  g_W00p + 52*2304, idUse);
    mma_stage(sStg + 2*STGB,   acc0, aOff, bOff);
    CP_WAIT1(); __syncthreads();                               // s=51
    stage(2*STGB, 32, g_W00p + 53*2304, idUse);
    mma_stage(sStg,            acc0, aOff, bOff);
    CP_WAIT1(); __syncthreads();                               // s=52
    stage(0,      0,  g_W10p,           selfIdx);
    mma_stage(sStg + STGB,     acc0, aOff, bOff);
    CP_WAIT1(); __syncthreads();                               // s=53
    stage(STGB,   32, g_W10p + 2304,    selfIdx);
    mma_stage(sStg + 2*STGB,   acc0, aOff, bOff);
    CP_WAIT1(); __syncthreads();                               // s=54
    mma_stage(sStg,            acc1, aOff, bOff);
    CP_WAIT0(); __syncthreads();                               // s=55
    mma_stage(sStg + STGB,     acc1, aOff, bOff);

    // epilogue: relu + bias -> h fp16
    #pragma unroll
    for (int mb = 0; mb < 2; ++mb) {
        const int r0 = wm * 32 + mb * 16 + (lane >> 2);
        const int p0 = base + r0, p1 = p0 + 8;
        #pragma unroll
        for (int nt = 0; nt < 4; ++nt) {
            const int col = wn * 32 + nt * 8 + (lane & 3) * 2;
            const float ba0 = __ldg(&b00[col]), ba1 = __ldg(&b00[col + 1]);
            const float bb0 = __ldg(&b10[col]), bb1 = __ldg(&b10[col + 1]);
            if (p0 < NPTS) {
                g_h16[(size_t)p0 * 64 + (col >> 1)] =
                    packh2(fmaxf(acc0[mb][nt][0] + ba0, 0.f), fmaxf(acc0[mb][nt][1] + ba1, 0.f));
                g_h16[(size_t)p0 * 64 + 32 + (col >> 1)] =
                    packh2(fmaxf(acc1[mb][nt][0] + bb0, 0.f), fmaxf(acc1[mb][nt][1] + bb1, 0.f));
            }
            if (p1 < NPTS) {
                g_h16[(size_t)p1 * 64 + (col >> 1)] =
                    packh2(fmaxf(acc0[mb][nt][2] + ba0, 0.f), fmaxf(acc0[mb][nt][3] + ba1, 0.f));
                g_h16[(size_t)p1 * 64 + 32 + (col >> 1)] =
                    packh2(fmaxf(acc1[mb][nt][2] + bb0, 0.f), fmaxf(acc1[mb][nt][3] + bb1, 0.f));
            }
        }
    }
}

// ==== kernel B: out = [conv0_1(h0)+b01 | relu(conv1_1(h1)+b11)@W12+b12] + x ====
__global__ __launch_bounds__(NTHR, 2)
void convB(const int* __restrict__ nbr,
           const float* __restrict__ b01, const float* __restrict__ b11,
           const float* __restrict__ b12, const float* __restrict__ x,
           float* __restrict__ out) {
    extern __shared__ unsigned sm[];
    const unsigned sStg = smem_u32(sm);
    const int tid = threadIdx.x, lane = tid & 31, warp = tid >> 5;
    const int wm = warp >> 1, wn = warp & 1;
    const int base = blockIdx.x * MT, rows = min(MT, NPTS - base);
    const int r = tid >> 1, q = tid & 1;
    const bool inval = (r >= rows);
    const int* nbrP = nbr + (size_t)(base + (inval ? 0 : r)) * K3;

    const unsigned aOff = (unsigned)((wm*32 + ((lane>>3)&1)*8 + (lane&7))*144 + ((lane>>4)&1)*16);
    const unsigned bOff = (unsigned)((wn*32 + ((lane>>4)&1)*8 + (lane&7))*144 + ((lane>>3)&1)*16);
    const unsigned dA0 = sStg + (unsigned)(r*144 + q*64);
    const int qw = q * 16;

    auto stage = [&](unsigned bufD, int kcw, const unsigned* wsrc, int idx) {
        const unsigned sz = (idx < NPTS) ? 16u : 0u;
        const unsigned* src = g_h16 + (size_t)(unsigned)idx * 64u + kcw + qw;
        const unsigned dA = dA0 + bufD;
        cp16(dA,      src,      sz);
        cp16(dA + 16, src + 4,  sz);
        cp16(dA + 32, src + 8,  sz);
        cp16(dA + 48, src + 12, sz);
        const unsigned wD = sStg + bufD + BOFFB + (unsigned)tid * 16u;
        const unsigned* ws = wsrc + tid * 4;
        cp16(wD,           ws,         16u);
        cp16(wD + 256*16u, ws + 256*4, 16u);
        if (tid < 64) cp16(wD + 512*16u, ws + 512*4, 16u);
        CP_COMMIT();
    };

    float acc0[2][4][4] = {};
    float acc1[2][4][4] = {};

    int idUse = inval ? NPTS : __ldg(&nbrP[0]);
    int idPre = inval ? NPTS : __ldg(&nbrP[1]);
    stage(0, 0, g_Wcat, idUse);
    stage(STGB, 32, g_Wcat + 2304, idUse);

    const unsigned* wp = g_Wcat + 2 * 2304;
    for (int it = 0; it < 8; ++it) {
        #pragma unroll
        for (int u = 0; u < 6; ++u) {
            CP_WAIT1(); __syncthreads();
            if ((u & 1) == 0) {
                idUse = idPre;
                idPre = inval ? NPTS : __ldg(&nbrP[it * 3 + (u >> 1) + 2]);
            }
            stage(((u + 2) % 3) * STGB, (u & 1) * 32, wp + u * 2304, idUse);
            mma_stage(sStg + (u % 3) * STGB, (u & 1) ? acc1 : acc0, aOff, bOff);
        }
        wp += 6 * 2304;
    }
    // tail: stages 48..53
    CP_WAIT1(); __syncthreads();                               // s=48
    idUse = idPre; idPre = inval ? NPTS : __ldg(&nbrP[26]);
    stage(2*STGB, 0, g_Wcat + 50*2304, idUse);
    mma_stage(sStg,          acc0, aOff, bOff);
    CP_WAIT1(); __syncthreads();                               // s=49
    stage(0,      32, g_Wcat + 51*2304, idUse);
    mma_stage(sStg + STGB,   acc1, aOff, bOff);
    CP_WAIT1(); __syncthreads();                               // s=50
    idUse = idPre;
    stage(STGB,   0,  g_Wcat + 52*2304, idUse);
    mma_stage(sStg + 2*STGB, acc0, aOff, bOff);
    CP_WAIT1(); __syncthreads();                               // s=51
    stage(2*STGB, 32, g_Wcat + 53*2304, idUse);
    mma_stage(sStg,          acc1, aOff, bOff);
    CP_WAIT1(); __syncthreads();                               // s=52
    mma_stage(sStg + STGB,   acc0, aOff, bOff);
    CP_WAIT0(); __syncthreads();                               // s=53
    mma_stage(sStg + 2*STGB, acc1, aOff, bOff);

    // ---- epilogue: store out0 (+b01 +x); stage h1b = relu(acc1+b11) fp16 into buf0 A ----
    #pragma unroll
    for (int mb = 0; mb < 2; ++mb) {
        const int r0 = wm * 32 + mb * 16 + (lane >> 2), r1 = r0 + 8;
        const int p0 = base + r0, p1 = base + r1;
        #pragma unroll
        for (int nt = 0; nt < 4; ++nt) {
            const int col = wn * 32 + nt * 8 + (lane & 3) * 2;
            const float bh0 = __ldg(&b11[col]), bh1 = __ldg(&b11[col + 1]);
            sm[r0 * 36 + (col >> 1)] =
                packh2(fmaxf(acc1[mb][nt][0] + bh0, 0.f), fmaxf(acc1[mb][nt][1] + bh1, 0.f));
            sm[r1 * 36 + (col >> 1)] =
                packh2(fmaxf(acc1[mb][nt][2] + bh0, 0.f), fmaxf(acc1[mb][nt][3] + bh1, 0.f));
            const float bo0 = __ldg(&b01[col]), bo1 = __ldg(&b01[col + 1]);
            if (p0 < NPTS) {
                float2 xv = *(const float2*)(x + (size_t)p0 * 128 + col);
                *(float2*)(out + (size_t)p0 * 128 + col) =
                    make_float2(acc0[mb][nt][0] + bo0 + xv.x, acc0[mb][nt][1] + bo1 + xv.y);
            }
            if (p1 < NPTS) {
                float2 xv = *(const float2*)(x + (size_t)p1 * 128 + col);
                *(float2*)(out + (size_t)p1 * 128 + col) =
                    make_float2(acc0[mb][nt][2] + bo0 + xv.x, acc0[mb][nt][3] + bo1 + xv.y);
            }
        }
    }
    // copy W12 chunk image into buf0 B region
    #pragma unroll
    for (int j = 0; j < 3; ++j) {
        const int i = j * NTHR + tid;
        if (i < 576) ((uint4*)(sm + BOFFB / 4))[i] = ((const uint4*)g_W12p)[i];
    }
    __syncthreads();

    // ---- 1x1 epilogue GEMM: acc2 = h1b @ W12 ----
    float acc2[2][4][4] = {};
    mma_stage(sStg, acc2, aOff, bOff);

    #pragma unroll
    for (int mb = 0; mb < 2; ++mb) {
        const int r0 = wm * 32 + mb * 16 + (lane >> 2);
        const int p0 = base + r0, p1 = p0 + 8;
        #pragma unroll
        for (int nt = 0; nt < 4; ++nt) {
            const int col = wn * 32 + nt * 8 + (lane & 3) * 2;
            const float bv0 = __ldg(&b12[col]), bv1 = __ldg(&b12[col + 1]);
            if (p0 < NPTS) {
                float2 xv = *(const float2*)(x + (size_t)p0 * 128 + 64 + col);
                *(float2*)(out + (size_t)p0 * 128 + 64 + col) =
                    make_float2(acc2[mb][nt][0] + bv0 + xv.x, acc2[mb][nt][1] + bv1 + xv.y);
            }
            if (p1 < NPTS) {
                float2 xv = *(const float2*)(x + (size_t)p1 * 128 + 64 + col);
                *(float2*)(out + (size_t)p1 * 128 + 64 + col) =
                    make_float2(acc2[mb][nt][2] + bv0 + xv.x, acc2[mb][nt][3] + bv1 + xv.y);
            }
        }
    }
}

// ---------------- launch ----------------
extern "C" void kernel_launch(void* const* d_in, const int* in_sizes, int n_in,
                              void* d_out, int out_size) {
    const float* x   = (const float*)d_in[0];
    const int*   nbr = (const int*)  d_in[1];
    const float* W00 = (const float*)d_in[2];
    const float* b00 = (const float*)d_in[3];
    const float* W01 = (const float*)d_in[4];
    const float* b01 = (const float*)d_in[5];
    const float* W10 = (const float*)d_in[6];
    const float* b10 = (const float*)d_in[7];
    const float* W11 = (const float*)d_in[8];
    const float* b11 = (const float*)d_in[9];
    const float* W12 = (const float*)d_in[10];
    const float* b12 = (const float*)d_in[11];
    float* out = (float*)d_out;

    cudaFuncSetAttribute(convA, cudaFuncAttributeMaxDynamicSharedMemorySize, SMEM_BYTES);
    cudaFuncSetAttribute(convB, cudaFuncAttributeMaxDynamicSharedMemorySize, SMEM_BYTES);

    split_x<<<(NPTS * 32 + 255) / 256, 256>>>(x);
    pack_weights<<<(P_TOT + 255) / 256, 256>>>(W00, W01, W11, W10, W12);
    const int grid = (NPTS + MT - 1) / MT;   // 782
    convA<<<grid, NTHR, SMEM_BYTES>>>(nbr, b00, b10);
    convB<<<grid, NTHR, SMEM_BYTES>>>(nbr, b01, b11, b12, x, out);
}